// round 13
// baseline (speedup 1.0000x reference)
#include <cuda_runtime.h>
#include <math.h>
#include <stdint.h>

// Problem constants
#define Bb      2
#define Nn      2048
#define Cc      1024
#define Hh      16
#define Dd      64
#define MROWS   (Bb * Nn)      // 4096
#define THREEC  (3 * Cc)       // 3072
#define LOGMAX  4.6051701859880914f  // ln(100)
#define MASKNEG (-1e30f)

// ---------------------------------------------------------------------------
// Scratch
// ---------------------------------------------------------------------------
__device__ float g_qkv[(size_t)MROWS * THREEC];          // 50 MB
__device__ float g_att[(size_t)MROWS * Cc];              // 16 MB

// ---------------------------------------------------------------------------
// tf32 mma.sync helpers (sm_80+ PTX — safe under compute_103 family target)
// ---------------------------------------------------------------------------
__device__ __forceinline__ uint32_t f2t(float x) {
    uint32_t u;
    asm("cvt.rna.tf32.f32 %0, %1;" : "=r"(u) : "f"(x));
    return u;
}

__device__ __forceinline__ void mma8(float* d, const uint32_t* a, const uint32_t* b) {
    asm volatile(
        "mma.sync.aligned.m16n8k8.row.col.f32.tf32.tf32.f32 "
        "{%0,%1,%2,%3}, {%4,%5,%6,%7}, {%8,%9}, {%0,%1,%2,%3};"
        : "+f"(d[0]), "+f"(d[1]), "+f"(d[2]), "+f"(d[3])
        : "r"(a[0]), "r"(a[1]), "r"(a[2]), "r"(a[3]), "r"(b[0]), "r"(b[1]));
}
// Frag maps (g = lane>>2, tg = lane&3):
//   A: a0=(g,tg) a1=(g+8,tg) a2=(g,tg+4) a3=(g+8,tg+4)      [row, k]
//   B: b0=(k=tg,n=g) b1=(k=tg+4,n=g)                         [k, col]
//   C: c0=(g,2tg) c1=(g,2tg+1) c2=(g+8,2tg) c3=(g+8,2tg+1)   [row, col]

__device__ __forceinline__ uint32_t smem_u32(const void* p) {
    uint32_t a;
    asm("{ .reg .u64 t; cvta.to.shared.u64 t, %1; cvt.u32.u64 %0, t; }" : "=r"(a) : "l"(p));
    return a;
}
#define CP_ASYNC16(dst, src) \
    asm volatile("cp.async.cg.shared.global [%0], [%1], 16;" :: "r"(dst), "l"(src) : "memory")
#define CP_COMMIT()  asm volatile("cp.async.commit_group;" ::: "memory")
#define CP_WAIT0()   asm volatile("cp.async.wait_group 0;" ::: "memory")

// ===========================================================================
// NT GEMM, 2-stage pipelined: C[M][Nc] = A[M][K] * W[Nc][K]^T (+ bias)
// 256 thr, BM=128, BN=64, BK=16. Warp grid 4(m) x 2(n), warp tile 32x32.
// Next tile's LDGs issue before current tile's mma work; 1 sync per iter.
// ===========================================================================
#define PITCH 20

__global__ __launch_bounds__(256) void gemm_mma_nt(
    const float* __restrict__ A, const float* __restrict__ W,
    const float* __restrict__ bias, float* __restrict__ C,
    int M, int Nc, int K)
{
    __shared__ uint32_t As[2][128][PITCH];
    __shared__ uint32_t Bs[2][64][PITCH];
    const int tid = threadIdx.x;
    const int wid = tid >> 5, lane = tid & 31;
    const int g = lane >> 2, tg = lane & 3;
    const int wm = wid & 3, wn = wid >> 2;
    const int m0 = blockIdx.y * 128, n0 = blockIdx.x * 64;
    const int lr = tid >> 2, lc = tid & 3;

    float4 av0, av1, wv;   // staging

    auto g_load = [&](int kt) {
        av0 = *reinterpret_cast<const float4*>(&A[(size_t)(m0 + lr) * K + kt + lc * 4]);
        av1 = *reinterpret_cast<const float4*>(&A[(size_t)(m0 + lr + 64) * K + kt + lc * 4]);
        wv  = *reinterpret_cast<const float4*>(&W[(size_t)(n0 + lr) * K + kt + lc * 4]);
    };
    auto g_store = [&](int bf) {
        uint4 t0 = {f2t(av0.x), f2t(av0.y), f2t(av0.z), f2t(av0.w)};
        uint4 t1 = {f2t(av1.x), f2t(av1.y), f2t(av1.z), f2t(av1.w)};
        uint4 t2 = {f2t(wv.x),  f2t(wv.y),  f2t(wv.z),  f2t(wv.w)};
        *reinterpret_cast<uint4*>(&As[bf][lr][lc * 4]) = t0;
        *reinterpret_cast<uint4*>(&As[bf][lr + 64][lc * 4]) = t1;
        *reinterpret_cast<uint4*>(&Bs[bf][lr][lc * 4]) = t2;
    };

    float acc[2][4][4] = {};

    g_load(0);
    g_store(0);
    __syncthreads();

    const int nk = K >> 4;
    for (int i = 0; i < nk; ++i) {
        const int cur = i & 1;
        if (i + 1 < nk) g_load((i + 1) << 4);          // LDG in flight over compute

        #pragma unroll
        for (int ks = 0; ks < 2; ++ks) {
            const int k0 = ks * 8;
            uint32_t af[2][4], bfr[4][2];
            #pragma unroll
            for (int mt = 0; mt < 2; ++mt) {
                const int rb = wm * 32 + mt * 16;
                af[mt][0] = As[cur][rb + g][k0 + tg];
                af[mt][1] = As[cur][rb + g + 8][k0 + tg];
                af[mt][2] = As[cur][rb + g][k0 + tg + 4];
                af[mt][3] = As[cur][rb + g + 8][k0 + tg + 4];
            }
            #pragma unroll
            for (int nt = 0; nt < 4; ++nt) {
                const int nb = wn * 32 + nt * 8;
                bfr[nt][0] = Bs[cur][nb + g][k0 + tg];
                bfr[nt][1] = Bs[cur][nb + g][k0 + tg + 4];
            }
            #pragma unroll
            for (int mt = 0; mt < 2; ++mt)
                #pragma unroll
                for (int nt = 0; nt < 4; ++nt)
                    mma8(acc[mt][nt], af[mt], bfr[nt]);
        }

        if (i + 1 < nk) g_store((i + 1) & 1);          // other buffer: safe (read i-1, sync passed)
        __syncthreads();
    }

    #pragma unroll
    for (int mt = 0; mt < 2; ++mt) {
        const int row = m0 + wm * 32 + mt * 16 + g;
        #pragma unroll
        for (int nt = 0; nt < 4; ++nt) {
            const int col = n0 + wn * 32 + nt * 8 + tg * 2;
            float2 v0 = {acc[mt][nt][0], acc[mt][nt][1]};
            float2 v1 = {acc[mt][nt][2], acc[mt][nt][3]};
            if (bias) {
                float b0 = bias[col], b1 = bias[col + 1];
                v0.x += b0; v0.y += b1; v1.x += b0; v1.y += b1;
            }
            *reinterpret_cast<float2*>(&C[(size_t)row * Nc + col]) = v0;
            *reinterpret_cast<float2*>(&C[(size_t)(row + 8) * Nc + col]) = v1;
        }
    }
}

// ---------------------------------------------------------------------------
// Normalize q and k head-rows (D=64) in place. One warp per (row, s, h).
// ---------------------------------------------------------------------------
__global__ __launch_bounds__(256) void norm_qk(float* __restrict__ qkv)
{
    int warp = (blockIdx.x * blockDim.x + threadIdx.x) >> 5;
    int lane = threadIdx.x & 31;
    int m = warp >> 5;
    int rem = warp & 31;
    int s = rem >> 4;
    int h = rem & 15;
    float* row = qkv + (size_t)m * THREEC + s * Cc + h * Dd;
    float v0 = row[lane], v1 = row[lane + 32];
    float ss = v0 * v0 + v1 * v1;
    #pragma unroll
    for (int o = 16; o; o >>= 1) ss += __shfl_xor_sync(0xffffffffu, ss, o);
    float inv = rsqrtf(ss);
    row[lane] = v0 * inv;
    row[lane + 32] = v1 * inv;
}

// ===========================================================================
// Fused flash attention with cp.async chunk prefetch.
// Per (bh, q-tile 64) block; k-chunks of 64 stream through smem.
// Dynamic smem layout (bytes):
//   KP   [64][68] u32   @ 0       (K tf32, reused for P)
//   Vs   [64][72] u32   @ 17408
//   Kraw [64][64] f32   @ 35840   (cp.async landing zone)
//   Vraw [64][64] f32   @ 52224
//   Ms   [64]     f32   @ 68608
// total 68864
// ===========================================================================
#define AT_KP    0
#define AT_VS    17408
#define AT_KRAW  35840
#define AT_VRAW  52224
#define AT_MS    68608
#define AT_TOTAL 68864

// Issue cp.async prefetch of one 64-row K/V chunk into the raw landing zones.
__device__ __forceinline__ void issue_chunk(
    float (*Kraw)[64], float (*Vraw)[64],
    int b, int h, int kt, int cr, int cc4)
{
    #pragma unroll
    for (int i = 0; i < 8; ++i) {
        int r = cr + i * 8;
        const float* base = &g_qkv[(size_t)(b * Nn + kt + r) * THREEC + h * Dd + cc4 * 4];
        CP_ASYNC16(smem_u32(&Kraw[r][cc4 * 4]), base + Cc);
        CP_ASYNC16(smem_u32(&Vraw[r][cc4 * 4]), base + 2 * Cc);
    }
    CP_COMMIT();
}

__global__ __launch_bounds__(128) void attn_fused(
    const float* __restrict__ alibi,
    const int* __restrict__ mask,
    const float* __restrict__ logit_scale)
{
    extern __shared__ char sm[];
    uint32_t (*KP)[68]   = reinterpret_cast<uint32_t(*)[68]>(sm + AT_KP);
    uint32_t (*Vs)[72]   = reinterpret_cast<uint32_t(*)[72]>(sm + AT_VS);
    float    (*Kraw)[64] = reinterpret_cast<float(*)[64]>(sm + AT_KRAW);
    float    (*Vraw)[64] = reinterpret_cast<float(*)[64]>(sm + AT_VRAW);
    float    *Ms         = reinterpret_cast<float*>(sm + AT_MS);

    const int tid = threadIdx.x;
    const int wid = tid >> 5, lane = tid & 31;
    const int g = lane >> 2, tg = lane & 3;
    const int wq = wid * 16;
    const int bh = blockIdx.y, b = bh >> 4, h = bh & 15;
    const int q0 = blockIdx.x * 64;
    const float sc = __expf(fminf(logit_scale[h], LOGMAX));

    const int cr = tid >> 4;       // loader row base (rows cr + 8i)
    const int cc4 = tid & 15;      // loader float4 column

    // ---- stage Q tile into KP, pull A-frags into registers ----
    #pragma unroll
    for (int i = 0; i < 8; ++i) {
        int r = cr + i * 8;
        float4 qv = *reinterpret_cast<const float4*>(
            &g_qkv[(size_t)(b * Nn + q0 + r) * THREEC + h * Dd + cc4 * 4]);
        uint4 t = {f2t(qv.x), f2t(qv.y), f2t(qv.z), f2t(qv.w)};
        *reinterpret_cast<uint4*>(&KP[r][cc4 * 4]) = t;
    }
    issue_chunk(Kraw, Vraw, b, h, 0, cr, cc4);     // prefetch first K/V chunk
    __syncthreads();
    uint32_t qf[8][4];
    #pragma unroll
    for (int ks = 0; ks < 8; ++ks) {
        qf[ks][0] = KP[wq + g][ks * 8 + tg];
        qf[ks][1] = KP[wq + g + 8][ks * 8 + tg];
        qf[ks][2] = KP[wq + g][ks * 8 + tg + 4];
        qf[ks][3] = KP[wq + g + 8][ks * 8 + tg + 4];
    }

    float m0r = MASKNEG, m1r = MASKNEG, l0 = 0.f, l1 = 0.f;
    float acc_o[8][4] = {};

    const float* al0 = &alibi[((size_t)bh * Nn + q0 + wq + g) * Nn];
    const float* al1 = al0 + (size_t)8 * Nn;

    for (int kt = 0; kt < Nn; kt += 64) {
        CP_WAIT0();
        __syncthreads();   // raw chunk ready; prior PV reads of KP/Vs complete

        // ---- convert raw -> tf32 tiles ----
        #pragma unroll
        for (int i = 0; i < 8; ++i) {
            int r = cr + i * 8;
            float4 kv = *reinterpret_cast<const float4*>(&Kraw[r][cc4 * 4]);
            float4 vv = *reinterpret_cast<const float4*>(&Vraw[r][cc4 * 4]);
            uint4 tk = {f2t(kv.x), f2t(kv.y), f2t(kv.z), f2t(kv.w)};
            uint4 tv = {f2t(vv.x), f2t(vv.y), f2t(vv.z), f2t(vv.w)};
            *reinterpret_cast<uint4*>(&KP[r][cc4 * 4]) = tk;
            *reinterpret_cast<uint4*>(&Vs[r][cc4 * 4]) = tv;
        }
        if (tid < 64) Ms[tid] = mask[b * Nn + kt + tid] ? MASKNEG : 0.f;
        __syncthreads();   // tiles visible; raw consumed

        if (kt + 64 < Nn)
            issue_chunk(Kraw, Vraw, b, h, kt + 64, cr, cc4);   // prefetch next over compute

        // ---- S = Q K^T ----
        float s[8][4] = {};
        #pragma unroll
        for (int nt = 0; nt < 8; ++nt) {
            #pragma unroll
            for (int ks = 0; ks < 8; ++ks) {
                uint32_t bfr[2];
                bfr[0] = KP[nt * 8 + g][ks * 8 + tg];
                bfr[1] = KP[nt * 8 + g][ks * 8 + tg + 4];
                mma8(s[nt], qf[ks], bfr);
            }
        }

        // ---- scale + alibi + mask; chunk row max ----
        float cm0 = MASKNEG, cm1 = MASKNEG;
        #pragma unroll
        for (int j = 0; j < 8; ++j) {
            const int col = j * 8 + tg * 2;
            float2 a0 = *reinterpret_cast<const float2*>(&al0[kt + col]);
            float2 a1 = *reinterpret_cast<const float2*>(&al1[kt + col]);
            float msk0 = Ms[col], msk1 = Ms[col + 1];
            s[j][0] = fmaf(s[j][0], sc, a0.x + msk0);
            s[j][1] = fmaf(s[j][1], sc, a0.y + msk1);
            s[j][2] = fmaf(s[j][2], sc, a1.x + msk0);
            s[j][3] = fmaf(s[j][3], sc, a1.y + msk1);
            cm0 = fmaxf(cm0, fmaxf(s[j][0], s[j][1]));
            cm1 = fmaxf(cm1, fmaxf(s[j][2], s[j][3]));
        }
        cm0 = fmaxf(cm0, __shfl_xor_sync(0xffffffffu, cm0, 1));
        cm0 = fmaxf(cm0, __shfl_xor_sync(0xffffffffu, cm0, 2));
        cm1 = fmaxf(cm1, __shfl_xor_sync(0xffffffffu, cm1, 1));
        cm1 = fmaxf(cm1, __shfl_xor_sync(0xffffffffu, cm1, 2));

        const float nm0 = fmaxf(m0r, cm0), nm1 = fmaxf(m1r, cm1);
        const float f0 = __expf(m0r - nm0), f1 = __expf(m1r - nm1);
        m0r = nm0; m1r = nm1;

        float rs0 = 0.f, rs1 = 0.f;
        #pragma unroll
        for (int j = 0; j < 8; ++j) {
            s[j][0] = __expf(s[j][0] - nm0); rs0 += s[j][0];
            s[j][1] = __expf(s[j][1] - nm0); rs0 += s[j][1];
            s[j][2] = __expf(s[j][2] - nm1); rs1 += s[j][2];
            s[j][3] = __expf(s[j][3] - nm1); rs1 += s[j][3];
        }
        rs0 += __shfl_xor_sync(0xffffffffu, rs0, 1);
        rs0 += __shfl_xor_sync(0xffffffffu, rs0, 2);
        rs1 += __shfl_xor_sync(0xffffffffu, rs1, 1);
        rs1 += __shfl_xor_sync(0xffffffffu, rs1, 2);
        l0 = l0 * f0 + rs0;
        l1 = l1 * f1 + rs1;

        #pragma unroll
        for (int j = 0; j < 8; ++j) {
            acc_o[j][0] *= f0; acc_o[j][1] *= f0;
            acc_o[j][2] *= f1; acc_o[j][3] *= f1;
        }

        __syncthreads();   // all warps done reading K from KP
        #pragma unroll
        for (int j = 0; j < 8; ++j) {
            KP[wq + g][j * 8 + tg * 2]         = f2t(s[j][0]);
            KP[wq + g][j * 8 + tg * 2 + 1]     = f2t(s[j][1]);
            KP[wq + g + 8][j * 8 + tg * 2]     = f2t(s[j][2]);
            KP[wq + g + 8][j * 8 + tg * 2 + 1] = f2t(s[j][3]);
        }
        __syncwarp();

        // ---- O += P V ----
        #pragma unroll
        for (int ks = 0; ks < 8; ++ks) {
            uint32_t pf[4];
            pf[0] = KP[wq + g][ks * 8 + tg];
            pf[1] = KP[wq + g + 8][ks * 8 + tg];
            pf[2] = KP[wq + g][ks * 8 + tg + 4];
            pf[3] = KP[wq + g + 8][ks * 8 + tg + 4];
            #pragma unroll
            for (int nt = 0; nt < 8; ++nt) {
                uint32_t bfr[2];
                bfr[0] = Vs[ks * 8 + tg][nt * 8 + g];
                bfr[1] = Vs[ks * 8 + tg + 4][nt * 8 + g];
                mma8(acc_o[nt], pf, bfr);
            }
        }
    }

    // ---- normalize and write O in [B,N,H*D] layout ----
    const float il0 = 1.0f / l0, il1 = 1.0f / l1;
    const size_t row0 = (size_t)(b * Nn + q0 + wq + g) * Cc + h * Dd;
    const size_t row1 = row0 + (size_t)8 * Cc;
    #pragma unroll
    for (int j = 0; j < 8; ++j) {
        const int col = j * 8 + tg * 2;
        float2 v0 = {acc_o[j][0] * il0, acc_o[j][1] * il0};
        float2 v1 = {acc_o[j][2] * il1, acc_o[j][3] * il1};
        *reinterpret_cast<float2*>(&g_att[row0 + col]) = v0;
        *reinterpret_cast<float2*>(&g_att[row1 + col]) = v1;
    }
}

// ---------------------------------------------------------------------------
// Launch
// ---------------------------------------------------------------------------
extern "C" void kernel_launch(void* const* d_in, const int* in_sizes, int n_in,
                              void* d_out, int out_size)
{
    const float* x           = (const float*)d_in[0];
    const int*   pad_mask    = (const int*)d_in[1];
    const float* alibi       = (const float*)d_in[2];
    const float* qkv_w       = (const float*)d_in[3];
    const float* proj_w      = (const float*)d_in[4];
    const float* proj_b      = (const float*)d_in[5];
    const float* logit_scale = (const float*)d_in[6];
    float*       out         = (float*)d_out;

    void *qkvp = nullptr, *attp = nullptr;
    cudaGetSymbolAddress(&qkvp, g_qkv);
    cudaGetSymbolAddress(&attp, g_att);

    static int attr_set = 0;
    if (!attr_set) {
        cudaFuncSetAttribute(attn_fused, cudaFuncAttributeMaxDynamicSharedMemorySize, AT_TOTAL);
        attr_set = 1;
    }

    // 1. qkv projection (tf32 mma, pipelined)
    gemm_mma_nt<<<dim3(THREEC / 64, MROWS / 128), 256>>>(
        x, qkv_w, nullptr, (float*)qkvp, MROWS, THREEC, Cc);

    // 2. normalize q and k head-rows in place
    norm_qk<<<(MROWS * 2 * Hh) / 8, 256>>>((float*)qkvp);

    // 3-5. fused scores + softmax + PV (cp.async prefetch)
    attn_fused<<<dim3(Nn / 64, Bb * Hh), 128, AT_TOTAL>>>(alibi, pad_mask, logit_scale);

    // 6. output projection + bias (tf32 mma, pipelined)
    gemm_mma_nt<<<dim3(Cc / 64, MROWS / 128), 256>>>(
        (const float*)attp, proj_w, proj_b, out, MROWS, Cc, Cc);
}